// round 6
// baseline (speedup 1.0000x reference)
#include <cuda_runtime.h>
#include <stdint.h>

// TopK mask: out = x * (x in top-k of its row), ties -> lowest index.
// R6: split kernels. FAST (8 CTAs/SM, float-domain fixed-threshold select)
// handles ~100% of rows and flags failures; FIX (exact key-domain radix
// select) repairs flagged rows. Flags written every call -> deterministic
// across graph replays.

#define F_DIM 4096
#define TPB   256
#define CAP   192   // candidate capacity; count(x>=2.0) ~ 93 +- 9.5 for N(0,1)

__device__ unsigned char g_flag[65536];

static __device__ __forceinline__ unsigned f2key(unsigned u) {
    return u ^ ((unsigned)((int)u >> 31) | 0x80000000u);
}

// ============================ FAST KERNEL ============================
__global__ __launch_bounds__(TPB, 8)
void topk_fast_kernel(const float* __restrict__ x,
                      const int*   __restrict__ kptr,
                      int kfallback,
                      float* __restrict__ out)
{
    const int tid  = threadIdx.x;
    const int lane = tid & 31;
    const int wid  = tid >> 5;
    const size_t row = blockIdx.x;

    __shared__ __align__(16) float s_cand[CAP + 2];
    __shared__ unsigned s_wcnt[8];
    __shared__ unsigned s_red[8];
    __shared__ unsigned s_ctrl[2];    // [0]=Kstar bits  [1]=winner count

    const float4* __restrict__ xr   = reinterpret_cast<const float4*>(x) + row * (F_DIM / 4);
    float4*       __restrict__ orow = reinterpret_cast<float4*>(out)     + row * (F_DIM / 4);

    const int kv = (kptr != nullptr) ? __ldg(kptr) : kfallback;

    if (kv <= 0) {
        float4 z; z.x = z.y = z.z = z.w = 0.0f;
        #pragma unroll
        for (int i = 0; i < 4; ++i) orow[tid + i * 256] = z;
        if (tid == 0) g_flag[row] = 0;
        return;
    }
    if (kv >= F_DIM) {
        orow[tid      ] = __ldg(xr + tid);
        orow[tid + 256] = __ldg(xr + tid + 256);
        orow[tid + 512] = __ldg(xr + tid + 512);
        orow[tid + 768] = __ldg(xr + tid + 768);
        if (tid == 0) g_flag[row] = 0;
        return;
    }
    const unsigned K = (unsigned)kv;
    const float T = 2.0f;

    // ---- pass 1: count + atomic-free compaction of candidates >= T ----
    unsigned n_c;
    {
        float4 a0 = __ldg(xr + tid);
        float4 a1 = __ldg(xr + tid + 256);
        float4 a2 = __ldg(xr + tid + 512);
        float4 a3 = __ldg(xr + tid + 768);

        unsigned cnt = 0;
        cnt += (a0.x >= T); cnt += (a0.y >= T); cnt += (a0.z >= T); cnt += (a0.w >= T);
        cnt += (a1.x >= T); cnt += (a1.y >= T); cnt += (a1.z >= T); cnt += (a1.w >= T);
        cnt += (a2.x >= T); cnt += (a2.y >= T); cnt += (a2.z >= T); cnt += (a2.w >= T);
        cnt += (a3.x >= T); cnt += (a3.y >= T); cnt += (a3.z >= T); cnt += (a3.w >= T);

        unsigned incl = cnt;
        #pragma unroll
        for (int d = 1; d < 32; d <<= 1) {
            unsigned nb = __shfl_up_sync(0xffffffffu, incl, d);
            if (lane >= d) incl += nb;
        }
        if (lane == 31) s_wcnt[wid] = incl;
        if (tid == 0)   s_ctrl[1] = 0u;
        __syncthreads();

        unsigned base = 0, tot = 0;
        #pragma unroll
        for (int w = 0; w < 8; ++w) {
            unsigned t = s_wcnt[w];
            tot += t;
            if (w < wid) base += t;
        }
        n_c = tot;
        if (n_c < K || n_c > CAP) {           // distribution failure -> fixup
            if (tid == 0) g_flag[row] = 1;
            return;
        }
        unsigned pos = base + (incl - cnt);
        if (a0.x >= T) s_cand[pos++] = a0.x;
        if (a0.y >= T) s_cand[pos++] = a0.y;
        if (a0.z >= T) s_cand[pos++] = a0.z;
        if (a0.w >= T) s_cand[pos++] = a0.w;
        if (a1.x >= T) s_cand[pos++] = a1.x;
        if (a1.y >= T) s_cand[pos++] = a1.y;
        if (a1.z >= T) s_cand[pos++] = a1.z;
        if (a1.w >= T) s_cand[pos++] = a1.w;
        if (a2.x >= T) s_cand[pos++] = a2.x;
        if (a2.y >= T) s_cand[pos++] = a2.y;
        if (a2.z >= T) s_cand[pos++] = a2.z;
        if (a2.w >= T) s_cand[pos++] = a2.w;
        if (a3.x >= T) s_cand[pos++] = a3.x;
        if (a3.y >= T) s_cand[pos++] = a3.y;
        if (a3.z >= T) s_cand[pos++] = a3.z;
        if (a3.w >= T) s_cand[pos++] = a3.w;
        if (tid == 0) {                       // pad for float2 pair loads
            s_cand[n_c]     = __int_as_float(0xff800000);
            s_cand[n_c + 1] = __int_as_float(0xff800000);
        }
    }
    __syncthreads();

    // ---- gt-only rank scan: winner has exactly K-1 candidates above it ----
    if ((unsigned)tid < n_c) {
        float c = s_cand[tid];
        unsigned gt = 0;
        const float2* p2 = reinterpret_cast<const float2*>(s_cand);
        const unsigned np = (n_c + 1u) >> 1;
        #pragma unroll 4
        for (unsigned jp = 0; jp < np; ++jp) {
            float2 w2 = p2[jp];
            gt += (w2.x > c);
            gt += (w2.y > c);
        }
        if (gt == K - 1u) {
            atomicAdd(&s_ctrl[1], 1u);
            s_ctrl[0] = __float_as_uint(c);   // duplicates write identical bits
        }
    }
    __syncthreads();

    const unsigned m = s_ctrl[1];
    if (m == 0u) {                            // tie group straddles K -> fixup
        if (tid == 0) g_flag[row] = 1;
        return;
    }
    const float Ks = __uint_as_float(s_ctrl[0]);

    if (m == 1u) {
        // common case: keep iff v >= Ks
        #pragma unroll
        for (int i = 0; i < 4; ++i) {
            float4 v4 = __ldg(xr + tid + i * 256);
            float4 o;
            o.x = (v4.x >= Ks) ? v4.x : 0.0f;
            o.y = (v4.y >= Ks) ? v4.y : 0.0f;
            o.z = (v4.z >= Ks) ? v4.z : 0.0f;
            o.w = (v4.w >= Ks) ? v4.w : 0.0f;
            orow[tid + i * 256] = o;
        }
        if (tid == 0) g_flag[row] = 0;
        return;
    }

    // m > 1: budget is exactly 1 equal element -> keep lowest-index == Ks
    unsigned Ccut;
    {
        unsigned mc = 0xFFFFFFFFu;
        #pragma unroll
        for (int i = 0; i < 4; ++i) {
            float4 v4 = __ldg(xr + tid + i * 256);
            unsigned col0 = (unsigned)((i << 10) + (tid << 2));
            if (v4.x == Ks) mc = min(mc, col0 + 0u);
            if (v4.y == Ks) mc = min(mc, col0 + 1u);
            if (v4.z == Ks) mc = min(mc, col0 + 2u);
            if (v4.w == Ks) mc = min(mc, col0 + 3u);
        }
        mc = __reduce_min_sync(0xffffffffu, mc);
        if (lane == 0) s_red[wid] = mc;
        __syncthreads();
        unsigned mm = 0xFFFFFFFFu;
        #pragma unroll
        for (int w = 0; w < 8; ++w) mm = min(mm, s_red[w]);
        Ccut = mm;
    }
    #pragma unroll
    for (int i = 0; i < 4; ++i) {
        float4 v4 = __ldg(xr + tid + i * 256);
        unsigned col0 = (unsigned)((i << 10) + (tid << 2));
        float4 o;
        o.x = ((v4.x > Ks) || (v4.x == Ks && (col0 + 0u) <= Ccut)) ? v4.x : 0.0f;
        o.y = ((v4.y > Ks) || (v4.y == Ks && (col0 + 1u) <= Ccut)) ? v4.y : 0.0f;
        o.z = ((v4.z > Ks) || (v4.z == Ks && (col0 + 2u) <= Ccut)) ? v4.z : 0.0f;
        o.w = ((v4.w > Ks) || (v4.w == Ks && (col0 + 3u) <= Ccut)) ? v4.w : 0.0f;
        orow[tid + i * 256] = o;
    }
    if (tid == 0) g_flag[row] = 0;
}

// ============================ FIX KERNEL =============================
// Exact key-domain radix select for flagged rows (rare / adversarial data).
__global__ __launch_bounds__(TPB, 4)
void topk_fix_kernel(const float* __restrict__ x,
                     const int*   __restrict__ kptr,
                     int kfallback,
                     float* __restrict__ out)
{
    const size_t row = blockIdx.x;
    if (g_flag[row] == 0) return;             // broadcast load, ~all rows exit

    const int tid  = threadIdx.x;
    const int lane = tid & 31;
    const int wid  = tid >> 5;

    __shared__ unsigned s_ckey[CAP];
    __shared__ unsigned s_warp[8][4];
    __shared__ unsigned s_ctrl[8];   // [0]=Kstar [2]=c_ge [3]=c_gt [7]=cand ctr

    const uint4* __restrict__ xu = reinterpret_cast<const uint4*>(x) + row * (F_DIM / 4);
    uint4*       __restrict__ ou = reinterpret_cast<uint4*>(out)     + row * (F_DIM / 4);

    const int kv = (kptr != nullptr) ? __ldg(kptr) : kfallback;
    const unsigned K = (unsigned)kv;   // flagged rows always have 0 < kv < F_DIM

    unsigned lo = 0u, cnt_lo = F_DIM, cnt_hi1 = 0u;
    int shift = 32;

    #pragma unroll 1
    while (cnt_lo - cnt_hi1 > CAP && shift > 0) {
        unsigned q = 1u << (shift - 2);
        unsigned t1 = lo + q, t2 = lo + 2u * q, t3 = lo + 3u * q;
        unsigned c1 = 0, c2 = 0, c3 = 0;
        {
            uint4 b0 = __ldg(xu + tid), b1 = __ldg(xu + tid + 256),
                  b2 = __ldg(xu + tid + 512), b3 = __ldg(xu + tid + 768);
            unsigned key[16] = { f2key(b0.x),f2key(b0.y),f2key(b0.z),f2key(b0.w),
                                 f2key(b1.x),f2key(b1.y),f2key(b1.z),f2key(b1.w),
                                 f2key(b2.x),f2key(b2.y),f2key(b2.z),f2key(b2.w),
                                 f2key(b3.x),f2key(b3.y),f2key(b3.z),f2key(b3.w) };
            #pragma unroll
            for (int e = 0; e < 16; ++e) {
                c1 += (key[e] >= t1);
                c2 += (key[e] >= t2);
                c3 += (key[e] >= t3);
            }
        }
        c1 = __reduce_add_sync(0xffffffffu, c1);
        c2 = __reduce_add_sync(0xffffffffu, c2);
        c3 = __reduce_add_sync(0xffffffffu, c3);
        if (lane == 0) { s_warp[wid][0] = c1; s_warp[wid][1] = c2; s_warp[wid][2] = c3; }
        __syncthreads();
        unsigned C1 = 0, C2 = 0, C3 = 0;
        #pragma unroll
        for (int w = 0; w < 8; ++w) { C1 += s_warp[w][0]; C2 += s_warp[w][1]; C3 += s_warp[w][2]; }
        __syncthreads();
        if      (C3 >= K) { lo = t3; cnt_lo = C3; }
        else if (C2 >= K) { lo = t2; cnt_lo = C2; cnt_hi1 = C3; }
        else if (C1 >= K) { lo = t1; cnt_lo = C1; cnt_hi1 = C2; }
        else              {                      cnt_hi1 = C1; }
        shift -= 2;
    }

    unsigned Kstar, c_ge, c_gt;
    if (shift == 0) {
        Kstar = lo; c_ge = cnt_lo; c_gt = cnt_hi1;
    } else {
        if (tid == 0) s_ctrl[7] = 0u;
        __syncthreads();
        const unsigned hib = lo + ((1u << shift) - 1u);
        {
            uint4 b0 = __ldg(xu + tid), b1 = __ldg(xu + tid + 256),
                  b2 = __ldg(xu + tid + 512), b3 = __ldg(xu + tid + 768);
            unsigned key[16] = { f2key(b0.x),f2key(b0.y),f2key(b0.z),f2key(b0.w),
                                 f2key(b1.x),f2key(b1.y),f2key(b1.z),f2key(b1.w),
                                 f2key(b2.x),f2key(b2.y),f2key(b2.z),f2key(b2.w),
                                 f2key(b3.x),f2key(b3.y),f2key(b3.z),f2key(b3.w) };
            #pragma unroll
            for (int e = 0; e < 16; ++e) {
                bool in = (key[e] >= lo) && (key[e] <= hib);
                unsigned mk = __ballot_sync(0xffffffffu, in);
                unsigned base = 0u;
                if (lane == 0) base = atomicAdd(&s_ctrl[7], (unsigned)__popc(mk));
                base = __shfl_sync(0xffffffffu, base, 0);
                if (in) {
                    unsigned p = base + (unsigned)__popc(mk & ((1u << lane) - 1u));
                    if (p < CAP) s_ckey[p] = key[e];
                }
            }
        }
        __syncthreads();

        const unsigned nc = s_ctrl[7];
        const unsigned A  = cnt_hi1;
        if ((unsigned)tid < nc) {
            unsigned ck = s_ckey[tid];
            unsigned gt = 0, ge = 0;
            #pragma unroll 4
            for (unsigned j = 0; j < nc; ++j) {
                unsigned vv = s_ckey[j];
                gt += (vv >  ck);
                ge += (vv >= ck);
            }
            unsigned GT = A + gt, GE = A + ge;
            if (GT < K && GE >= K) { s_ctrl[0] = ck; s_ctrl[2] = GE; s_ctrl[3] = GT; }
        }
        __syncthreads();
        Kstar = s_ctrl[0]; c_ge = s_ctrl[2]; c_gt = s_ctrl[3];
    }

    unsigned Ccut = 0xFFFFFFFFu;
    {
        unsigned budget = K - c_gt;
        unsigned c_eq   = c_ge - c_gt;
        if (budget < c_eq) {
            int loB = 0, hiB = F_DIM - 1;
            #pragma unroll 1
            while (loB < hiB) {
                int mid = (loB + hiB) >> 1;
                unsigned cc = 0;
                {
                    uint4 b0 = __ldg(xu + tid), b1 = __ldg(xu + tid + 256),
                          b2 = __ldg(xu + tid + 512), b3 = __ldg(xu + tid + 768);
                    unsigned key[16] = { f2key(b0.x),f2key(b0.y),f2key(b0.z),f2key(b0.w),
                                         f2key(b1.x),f2key(b1.y),f2key(b1.z),f2key(b1.w),
                                         f2key(b2.x),f2key(b2.y),f2key(b2.z),f2key(b2.w),
                                         f2key(b3.x),f2key(b3.y),f2key(b3.z),f2key(b3.w) };
                    #pragma unroll
                    for (int e = 0; e < 16; ++e) {
                        int col = ((e >> 2) << 10) + (tid << 2) + (e & 3);
                        cc += (key[e] == Kstar && col <= mid) ? 1u : 0u;
                    }
                }
                cc = __reduce_add_sync(0xffffffffu, cc);
                if (lane == 0) s_warp[wid][0] = cc;
                __syncthreads();
                unsigned Ct = 0;
                #pragma unroll
                for (int w = 0; w < 8; ++w) Ct += s_warp[w][0];
                __syncthreads();
                if (Ct >= budget) hiB = mid; else loB = mid + 1;
            }
            Ccut = (unsigned)loB;
        }
    }

    {
        uint4 b0 = __ldg(xu + tid), b1 = __ldg(xu + tid + 256),
              b2 = __ldg(xu + tid + 512), b3 = __ldg(xu + tid + 768);
        uint4 bv[4] = {b0, b1, b2, b3};
        #pragma unroll
        for (int i = 0; i < 4; ++i) {
            unsigned col0 = (unsigned)((i << 10) + (tid << 2));
            unsigned u0 = bv[i].x, u1 = bv[i].y, u2v = bv[i].z, u3 = bv[i].w;
            unsigned k0 = f2key(u0), k1 = f2key(u1), k2 = f2key(u2v), k3 = f2key(u3);
            uint4 o;
            o.x = ((k0 > Kstar) || (k0 == Kstar && (col0 + 0u) <= Ccut)) ? u0  : 0u;
            o.y = ((k1 > Kstar) || (k1 == Kstar && (col0 + 1u) <= Ccut)) ? u1  : 0u;
            o.z = ((k2 > Kstar) || (k2 == Kstar && (col0 + 2u) <= Ccut)) ? u2v : 0u;
            o.w = ((k3 > Kstar) || (k3 == Kstar && (col0 + 3u) <= Ccut)) ? u3  : 0u;
            ou[tid + i * 256] = o;
        }
    }
}

extern "C" void kernel_launch(void* const* d_in, const int* in_sizes, int n_in,
                              void* d_out, int out_size)
{
    const float* x  = (const float*)d_in[0];
    const int*   kp = (n_in >= 2) ? (const int*)d_in[1] : nullptr;
    float* out = (float*)d_out;

    int B = in_sizes[0] / F_DIM;
    topk_fast_kernel<<<B, TPB>>>(x, kp, 64, out);
    topk_fix_kernel <<<B, TPB>>>(x, kp, 64, out);
}

// round 9
// speedup vs baseline: 1.1136x; 1.1136x over previous
#include <cuda_runtime.h>
#include <stdint.h>

// TopK mask: out = x * (x in top-k of its row), ties -> lowest index.
// R9: R6-proven two-kernel structure (per-row flag, no reset node, no
// gmem atomics). Fast kernel (8 CTAs/SM, float-domain fixed-threshold
// select) handles ~100% of rows and writes g_flag[row] 0/1 every call.
// Fix kernel uses ceil(B/128) CTAs; each scans 128 flags in one coalesced
// burst and exits immediately when none set (expected case), else runs the
// exact key-domain radix select on flagged rows.

#define F_DIM 4096
#define TPB   256
#define CAP   192      // candidate capacity; count(x>=2.0) ~ 93 +- 9.5 for N(0,1)
#define RPC   128      // rows per fix-kernel CTA

__device__ unsigned char g_flag[65536];

static __device__ __forceinline__ unsigned f2key(unsigned u) {
    return u ^ ((unsigned)((int)u >> 31) | 0x80000000u);
}

// ============================ FAST KERNEL ============================
__global__ __launch_bounds__(TPB, 8)
void topk_fast_kernel(const float* __restrict__ x,
                      const int*   __restrict__ kptr,
                      int kfallback,
                      float* __restrict__ out)
{
    const int tid  = threadIdx.x;
    const int lane = tid & 31;
    const int wid  = tid >> 5;
    const size_t row = blockIdx.x;

    __shared__ __align__(16) float s_cand[CAP + 2];
    __shared__ unsigned s_wcnt[8];
    __shared__ unsigned s_red[8];
    __shared__ unsigned s_ctrl[2];    // [0]=Kstar bits  [1]=winner count

    const float4* __restrict__ xr   = reinterpret_cast<const float4*>(x) + row * (F_DIM / 4);
    float4*       __restrict__ orow = reinterpret_cast<float4*>(out)     + row * (F_DIM / 4);

    const int kv = (kptr != nullptr) ? __ldg(kptr) : kfallback;

    if (kv <= 0) {
        float4 z; z.x = z.y = z.z = z.w = 0.0f;
        #pragma unroll
        for (int i = 0; i < 4; ++i) orow[tid + i * 256] = z;
        if (tid == 0) g_flag[row] = 0;
        return;
    }
    if (kv >= F_DIM) {
        orow[tid      ] = __ldg(xr + tid);
        orow[tid + 256] = __ldg(xr + tid + 256);
        orow[tid + 512] = __ldg(xr + tid + 512);
        orow[tid + 768] = __ldg(xr + tid + 768);
        if (tid == 0) g_flag[row] = 0;
        return;
    }
    const unsigned K = (unsigned)kv;
    const float T = 2.0f;

    // ---- pass 1: count + atomic-free compaction of candidates >= T ----
    unsigned n_c;
    {
        float4 a0 = __ldg(xr + tid);
        float4 a1 = __ldg(xr + tid + 256);
        float4 a2 = __ldg(xr + tid + 512);
        float4 a3 = __ldg(xr + tid + 768);

        unsigned cnt = 0;
        cnt += (a0.x >= T); cnt += (a0.y >= T); cnt += (a0.z >= T); cnt += (a0.w >= T);
        cnt += (a1.x >= T); cnt += (a1.y >= T); cnt += (a1.z >= T); cnt += (a1.w >= T);
        cnt += (a2.x >= T); cnt += (a2.y >= T); cnt += (a2.z >= T); cnt += (a2.w >= T);
        cnt += (a3.x >= T); cnt += (a3.y >= T); cnt += (a3.z >= T); cnt += (a3.w >= T);

        unsigned incl = cnt;
        #pragma unroll
        for (int d = 1; d < 32; d <<= 1) {
            unsigned nb = __shfl_up_sync(0xffffffffu, incl, d);
            if (lane >= d) incl += nb;
        }
        if (lane == 31) s_wcnt[wid] = incl;
        if (tid == 0)   s_ctrl[1] = 0u;
        __syncthreads();

        unsigned base = 0, tot = 0;
        #pragma unroll
        for (int w = 0; w < 8; ++w) {
            unsigned t = s_wcnt[w];
            tot += t;
            if (w < wid) base += t;
        }
        n_c = tot;
        if (n_c < K || n_c > CAP) {           // distribution failure -> flag
            if (tid == 0) g_flag[row] = 1;
            return;
        }
        unsigned pos = base + (incl - cnt);
        if (a0.x >= T) s_cand[pos++] = a0.x;
        if (a0.y >= T) s_cand[pos++] = a0.y;
        if (a0.z >= T) s_cand[pos++] = a0.z;
        if (a0.w >= T) s_cand[pos++] = a0.w;
        if (a1.x >= T) s_cand[pos++] = a1.x;
        if (a1.y >= T) s_cand[pos++] = a1.y;
        if (a1.z >= T) s_cand[pos++] = a1.z;
        if (a1.w >= T) s_cand[pos++] = a1.w;
        if (a2.x >= T) s_cand[pos++] = a2.x;
        if (a2.y >= T) s_cand[pos++] = a2.y;
        if (a2.z >= T) s_cand[pos++] = a2.z;
        if (a2.w >= T) s_cand[pos++] = a2.w;
        if (a3.x >= T) s_cand[pos++] = a3.x;
        if (a3.y >= T) s_cand[pos++] = a3.y;
        if (a3.z >= T) s_cand[pos++] = a3.z;
        if (a3.w >= T) s_cand[pos++] = a3.w;
        if (tid == 0) {                       // pad for float2 pair loads
            s_cand[n_c]     = __int_as_float(0xff800000);
            s_cand[n_c + 1] = __int_as_float(0xff800000);
        }
    }
    __syncthreads();

    // ---- gt-only rank scan: winner has exactly K-1 candidates above it ----
    if ((unsigned)tid < n_c) {
        float c = s_cand[tid];
        unsigned gt = 0;
        const float2* p2 = reinterpret_cast<const float2*>(s_cand);
        const unsigned np = (n_c + 1u) >> 1;
        #pragma unroll 4
        for (unsigned jp = 0; jp < np; ++jp) {
            float2 w2 = p2[jp];
            gt += (w2.x > c);
            gt += (w2.y > c);
        }
        if (gt == K - 1u) {
            atomicAdd(&s_ctrl[1], 1u);
            s_ctrl[0] = __float_as_uint(c);   // duplicates write identical bits
        }
    }
    __syncthreads();

    const unsigned m = s_ctrl[1];
    if (m == 0u) {                            // tie group straddles K -> flag
        if (tid == 0) g_flag[row] = 1;
        return;
    }
    const float Ks = __uint_as_float(s_ctrl[0]);

    if (m == 1u) {
        // common case: keep iff v >= Ks
        #pragma unroll
        for (int i = 0; i < 4; ++i) {
            float4 v4 = __ldg(xr + tid + i * 256);
            float4 o;
            o.x = (v4.x >= Ks) ? v4.x : 0.0f;
            o.y = (v4.y >= Ks) ? v4.y : 0.0f;
            o.z = (v4.z >= Ks) ? v4.z : 0.0f;
            o.w = (v4.w >= Ks) ? v4.w : 0.0f;
            orow[tid + i * 256] = o;
        }
        if (tid == 0) g_flag[row] = 0;
        return;
    }

    // m > 1: budget is exactly 1 equal element -> keep lowest-index == Ks
    unsigned Ccut;
    {
        unsigned mc = 0xFFFFFFFFu;
        #pragma unroll
        for (int i = 0; i < 4; ++i) {
            float4 v4 = __ldg(xr + tid + i * 256);
            unsigned col0 = (unsigned)((i << 10) + (tid << 2));
            if (v4.x == Ks) mc = min(mc, col0 + 0u);
            if (v4.y == Ks) mc = min(mc, col0 + 1u);
            if (v4.z == Ks) mc = min(mc, col0 + 2u);
            if (v4.w == Ks) mc = min(mc, col0 + 3u);
        }
        mc = __reduce_min_sync(0xffffffffu, mc);
        if (lane == 0) s_red[wid] = mc;
        __syncthreads();
        unsigned mm = 0xFFFFFFFFu;
        #pragma unroll
        for (int w = 0; w < 8; ++w) mm = min(mm, s_red[w]);
        Ccut = mm;
    }
    #pragma unroll
    for (int i = 0; i < 4; ++i) {
        float4 v4 = __ldg(xr + tid + i * 256);
        unsigned col0 = (unsigned)((i << 10) + (tid << 2));
        float4 o;
        o.x = ((v4.x > Ks) || (v4.x == Ks && (col0 + 0u) <= Ccut)) ? v4.x : 0.0f;
        o.y = ((v4.y > Ks) || (v4.y == Ks && (col0 + 1u) <= Ccut)) ? v4.y : 0.0f;
        o.z = ((v4.z > Ks) || (v4.z == Ks && (col0 + 2u) <= Ccut)) ? v4.z : 0.0f;
        o.w = ((v4.w > Ks) || (v4.w == Ks && (col0 + 3u) <= Ccut)) ? v4.w : 0.0f;
        orow[tid + i * 256] = o;
    }
    if (tid == 0) g_flag[row] = 0;
}

// ============================ FIX KERNEL =============================
// ceil(B/RPC) CTAs. Each scans RPC contiguous flags (coalesced) and runs
// the exact key-domain radix select on flagged rows. Expected: no flags
// set -> each CTA retires after one load + two barriers.
__global__ __launch_bounds__(TPB, 8)
void topk_fix_kernel(const float* __restrict__ x,
                     const int*   __restrict__ kptr,
                     int kfallback, int B,
                     float* __restrict__ out)
{
    const int tid  = threadIdx.x;
    const int lane = tid & 31;
    const int wid  = tid >> 5;

    __shared__ int s_rows[RPC];
    __shared__ int s_nrows;
    __shared__ unsigned s_ckey[CAP];
    __shared__ unsigned s_warp[8][4];
    __shared__ unsigned s_ctrl[8];   // [0]=Kstar [2]=c_ge [3]=c_gt [7]=cand ctr

    // ---- gather flagged rows in this CTA's stripe ----
    if (tid == 0) s_nrows = 0;
    __syncthreads();
    if (tid < RPC) {
        int r = blockIdx.x * RPC + tid;
        if (r < B && g_flag[r] != 0) {
            int i = atomicAdd(&s_nrows, 1);
            s_rows[i] = r;
        }
    }
    __syncthreads();
    const int nrows = s_nrows;
    if (nrows == 0) return;                   // expected case

    const int kv = (kptr != nullptr) ? __ldg(kptr) : kfallback;
    const unsigned K = (unsigned)kv;   // flagged rows always have 0 < kv < F_DIM

    for (int li = 0; li < nrows; ++li) {
        const size_t row = (size_t)s_rows[li];
        const uint4* __restrict__ xu = reinterpret_cast<const uint4*>(x) + row * (F_DIM / 4);
        uint4*       __restrict__ ou = reinterpret_cast<uint4*>(out)     + row * (F_DIM / 4);

        unsigned lo = 0u, cnt_lo = F_DIM, cnt_hi1 = 0u;
        int shift = 32;

        #pragma unroll 1
        while (cnt_lo - cnt_hi1 > CAP && shift > 0) {
            unsigned q = 1u << (shift - 2);
            unsigned t1 = lo + q, t2 = lo + 2u * q, t3 = lo + 3u * q;
            unsigned c1 = 0, c2 = 0, c3 = 0;
            {
                uint4 b0 = __ldg(xu + tid), b1 = __ldg(xu + tid + 256),
                      b2 = __ldg(xu + tid + 512), b3 = __ldg(xu + tid + 768);
                unsigned key[16] = { f2key(b0.x),f2key(b0.y),f2key(b0.z),f2key(b0.w),
                                     f2key(b1.x),f2key(b1.y),f2key(b1.z),f2key(b1.w),
                                     f2key(b2.x),f2key(b2.y),f2key(b2.z),f2key(b2.w),
                                     f2key(b3.x),f2key(b3.y),f2key(b3.z),f2key(b3.w) };
                #pragma unroll
                for (int e = 0; e < 16; ++e) {
                    c1 += (key[e] >= t1);
                    c2 += (key[e] >= t2);
                    c3 += (key[e] >= t3);
                }
            }
            c1 = __reduce_add_sync(0xffffffffu, c1);
            c2 = __reduce_add_sync(0xffffffffu, c2);
            c3 = __reduce_add_sync(0xffffffffu, c3);
            if (lane == 0) { s_warp[wid][0] = c1; s_warp[wid][1] = c2; s_warp[wid][2] = c3; }
            __syncthreads();
            unsigned C1 = 0, C2 = 0, C3 = 0;
            #pragma unroll
            for (int w = 0; w < 8; ++w) { C1 += s_warp[w][0]; C2 += s_warp[w][1]; C3 += s_warp[w][2]; }
            __syncthreads();
            if      (C3 >= K) { lo = t3; cnt_lo = C3; }
            else if (C2 >= K) { lo = t2; cnt_lo = C2; cnt_hi1 = C3; }
            else if (C1 >= K) { lo = t1; cnt_lo = C1; cnt_hi1 = C2; }
            else              {                      cnt_hi1 = C1; }
            shift -= 2;
        }

        unsigned Kstar, c_ge, c_gt;
        if (shift == 0) {
            Kstar = lo; c_ge = cnt_lo; c_gt = cnt_hi1;
        } else {
            if (tid == 0) s_ctrl[7] = 0u;
            __syncthreads();
            const unsigned hib = lo + ((1u << shift) - 1u);
            {
                uint4 b0 = __ldg(xu + tid), b1 = __ldg(xu + tid + 256),
                      b2 = __ldg(xu + tid + 512), b3 = __ldg(xu + tid + 768);
                unsigned key[16] = { f2key(b0.x),f2key(b0.y),f2key(b0.z),f2key(b0.w),
                                     f2key(b1.x),f2key(b1.y),f2key(b1.z),f2key(b1.w),
                                     f2key(b2.x),f2key(b2.y),f2key(b2.z),f2key(b2.w),
                                     f2key(b3.x),f2key(b3.y),f2key(b3.z),f2key(b3.w) };
                #pragma unroll
                for (int e = 0; e < 16; ++e) {
                    bool in = (key[e] >= lo) && (key[e] <= hib);
                    unsigned mk = __ballot_sync(0xffffffffu, in);
                    unsigned base = 0u;
                    if (lane == 0) base = atomicAdd(&s_ctrl[7], (unsigned)__popc(mk));
                    base = __shfl_sync(0xffffffffu, base, 0);
                    if (in) {
                        unsigned p = base + (unsigned)__popc(mk & ((1u << lane) - 1u));
                        if (p < CAP) s_ckey[p] = key[e];
                    }
                }
            }
            __syncthreads();

            const unsigned nc = s_ctrl[7];
            const unsigned A  = cnt_hi1;
            if ((unsigned)tid < nc) {
                unsigned ck = s_ckey[tid];
                unsigned gt = 0, ge = 0;
                #pragma unroll 4
                for (unsigned j = 0; j < nc; ++j) {
                    unsigned vv = s_ckey[j];
                    gt += (vv >  ck);
                    ge += (vv >= ck);
                }
                unsigned GT = A + gt, GE = A + ge;
                if (GT < K && GE >= K) { s_ctrl[0] = ck; s_ctrl[2] = GE; s_ctrl[3] = GT; }
            }
            __syncthreads();
            Kstar = s_ctrl[0]; c_ge = s_ctrl[2]; c_gt = s_ctrl[3];
        }

        unsigned Ccut = 0xFFFFFFFFu;
        {
            unsigned budget = K - c_gt;
            unsigned c_eq   = c_ge - c_gt;
            if (budget < c_eq) {
                int loB = 0, hiB = F_DIM - 1;
                #pragma unroll 1
                while (loB < hiB) {
                    int mid = (loB + hiB) >> 1;
                    unsigned cc = 0;
                    {
                        uint4 b0 = __ldg(xu + tid), b1 = __ldg(xu + tid + 256),
                              b2 = __ldg(xu + tid + 512), b3 = __ldg(xu + tid + 768);
                        unsigned key[16] = { f2key(b0.x),f2key(b0.y),f2key(b0.z),f2key(b0.w),
                                             f2key(b1.x),f2key(b1.y),f2key(b1.z),f2key(b1.w),
                                             f2key(b2.x),f2key(b2.y),f2key(b2.z),f2key(b2.w),
                                             f2key(b3.x),f2key(b3.y),f2key(b3.z),f2key(b3.w) };
                        #pragma unroll
                        for (int e = 0; e < 16; ++e) {
                            int col = ((e >> 2) << 10) + (tid << 2) + (e & 3);
                            cc += (key[e] == Kstar && col <= mid) ? 1u : 0u;
                        }
                    }
                    cc = __reduce_add_sync(0xffffffffu, cc);
                    if (lane == 0) s_warp[wid][0] = cc;
                    __syncthreads();
                    unsigned Ct = 0;
                    #pragma unroll
                    for (int w = 0; w < 8; ++w) Ct += s_warp[w][0];
                    __syncthreads();
                    if (Ct >= budget) hiB = mid; else loB = mid + 1;
                }
                Ccut = (unsigned)loB;
            }
        }

        {
            uint4 b0 = __ldg(xu + tid), b1 = __ldg(xu + tid + 256),
                  b2 = __ldg(xu + tid + 512), b3 = __ldg(xu + tid + 768);
            uint4 bv[4] = {b0, b1, b2, b3};
            #pragma unroll
            for (int i = 0; i < 4; ++i) {
                unsigned col0 = (unsigned)((i << 10) + (tid << 2));
                unsigned u0 = bv[i].x, u1 = bv[i].y, u2v = bv[i].z, u3 = bv[i].w;
                unsigned k0 = f2key(u0), k1 = f2key(u1), k2 = f2key(u2v), k3 = f2key(u3);
                uint4 o;
                o.x = ((k0 > Kstar) || (k0 == Kstar && (col0 + 0u) <= Ccut)) ? u0  : 0u;
                o.y = ((k1 > Kstar) || (k1 == Kstar && (col0 + 1u) <= Ccut)) ? u1  : 0u;
                o.z = ((k2 > Kstar) || (k2 == Kstar && (col0 + 2u) <= Ccut)) ? u2v : 0u;
                o.w = ((k3 > Kstar) || (k3 == Kstar && (col0 + 3u) <= Ccut)) ? u3  : 0u;
                ou[tid + i * 256] = o;
            }
        }
        __syncthreads();   // reuse of shared buffers across list iterations
    }
}

extern "C" void kernel_launch(void* const* d_in, const int* in_sizes, int n_in,
                              void* d_out, int out_size)
{
    const float* x  = (const float*)d_in[0];
    const int*   kp = (n_in >= 2) ? (const int*)d_in[1] : nullptr;
    float* out = (float*)d_out;

    int B = in_sizes[0] / F_DIM;
    int fixg = (B + RPC - 1) / RPC;
    topk_fast_kernel<<<B, TPB>>>(x, kp, 64, out);
    topk_fix_kernel <<<fixg, TPB>>>(x, kp, 64, B, out);
}

// round 11
// speedup vs baseline: 1.1851x; 1.0642x over previous
#include <cuda_runtime.h>
#include <stdint.h>

// TopK mask: out = x * (x in top-k of its row), ties -> lowest index.
// R10: single kernel, 8 CTAs/SM. Hot path = R9 fast kernel (fixed
// threshold 2.0f, float-domain rank select). Cold path (wrong
// distribution / tie straddle) = exact key-domain radix select rewritten
// in STREAMING form (no register-resident key arrays) so the register
// ceiling stays at the hot path's requirement.

#define F_DIM 4096
#define TPB   256
#define CAP   192   // candidate capacity; count(x>=2.0) ~ 93 +- 9.5 for N(0,1)

static __device__ __forceinline__ unsigned f2key(unsigned u) {
    return u ^ ((unsigned)((int)u >> 31) | 0x80000000u);
}

__global__ __launch_bounds__(TPB, 8)
void topk_mask_kernel(const float* __restrict__ x,
                      const int*   __restrict__ kptr,
                      int kfallback,
                      float* __restrict__ out)
{
    const int tid  = threadIdx.x;
    const int lane = tid & 31;
    const int wid  = tid >> 5;
    const size_t row = blockIdx.x;

    __shared__ __align__(16) float s_cand[CAP + 2];   // cold path reuses as keys
    __shared__ unsigned s_wcnt[8];
    __shared__ unsigned s_warp[8][4];
    __shared__ unsigned s_ctrl[8];  // [0]=Kstar [1]=winner cnt [2]=c_ge [3]=c_gt [7]=cand ctr

    const float4* __restrict__ xr   = reinterpret_cast<const float4*>(x) + row * (F_DIM / 4);
    float4*       __restrict__ orow = reinterpret_cast<float4*>(out)     + row * (F_DIM / 4);

    const int kv = (kptr != nullptr) ? __ldg(kptr) : kfallback;

    if (kv <= 0) {
        float4 z; z.x = z.y = z.z = z.w = 0.0f;
        #pragma unroll
        for (int i = 0; i < 4; ++i) orow[tid + i * 256] = z;
        return;
    }
    if (kv >= F_DIM) {
        #pragma unroll
        for (int i = 0; i < 4; ++i) orow[tid + i * 256] = __ldg(xr + tid + i * 256);
        return;
    }
    const unsigned K = (unsigned)kv;
    const float T = 2.0f;

    bool fallback = false;

    // ================== HOT PATH: fixed threshold 2.0f ==================
    unsigned n_c;
    {
        float4 a0 = __ldg(xr + tid);
        float4 a1 = __ldg(xr + tid + 256);
        float4 a2 = __ldg(xr + tid + 512);
        float4 a3 = __ldg(xr + tid + 768);

        unsigned cnt = 0;
        cnt += (a0.x >= T); cnt += (a0.y >= T); cnt += (a0.z >= T); cnt += (a0.w >= T);
        cnt += (a1.x >= T); cnt += (a1.y >= T); cnt += (a1.z >= T); cnt += (a1.w >= T);
        cnt += (a2.x >= T); cnt += (a2.y >= T); cnt += (a2.z >= T); cnt += (a2.w >= T);
        cnt += (a3.x >= T); cnt += (a3.y >= T); cnt += (a3.z >= T); cnt += (a3.w >= T);

        unsigned incl = cnt;
        #pragma unroll
        for (int d = 1; d < 32; d <<= 1) {
            unsigned nb = __shfl_up_sync(0xffffffffu, incl, d);
            if (lane >= d) incl += nb;
        }
        if (lane == 31) s_wcnt[wid] = incl;
        if (tid == 0)   s_ctrl[1] = 0u;
        __syncthreads();

        unsigned base = 0, tot = 0;
        #pragma unroll
        for (int w = 0; w < 8; ++w) {
            unsigned t = s_wcnt[w];
            tot += t;
            if (w < wid) base += t;
        }
        n_c = tot;
        if (n_c < K || n_c > CAP) {
            fallback = true;                       // uniform across block
        } else {
            unsigned pos = base + (incl - cnt);
            if (a0.x >= T) s_cand[pos++] = a0.x;
            if (a0.y >= T) s_cand[pos++] = a0.y;
            if (a0.z >= T) s_cand[pos++] = a0.z;
            if (a0.w >= T) s_cand[pos++] = a0.w;
            if (a1.x >= T) s_cand[pos++] = a1.x;
            if (a1.y >= T) s_cand[pos++] = a1.y;
            if (a1.z >= T) s_cand[pos++] = a1.z;
            if (a1.w >= T) s_cand[pos++] = a1.w;
            if (a2.x >= T) s_cand[pos++] = a2.x;
            if (a2.y >= T) s_cand[pos++] = a2.y;
            if (a2.z >= T) s_cand[pos++] = a2.z;
            if (a2.w >= T) s_cand[pos++] = a2.w;
            if (a3.x >= T) s_cand[pos++] = a3.x;
            if (a3.y >= T) s_cand[pos++] = a3.y;
            if (a3.z >= T) s_cand[pos++] = a3.z;
            if (a3.w >= T) s_cand[pos++] = a3.w;
            if (tid == 0) {                        // pad for float2 pair loads
                s_cand[n_c]     = __int_as_float(0xff800000);
                s_cand[n_c + 1] = __int_as_float(0xff800000);
            }
        }
    }

    if (!fallback) {
        __syncthreads();
        // ---- gt-only rank scan: winner has exactly K-1 above it ----
        if ((unsigned)tid < n_c) {
            float c = s_cand[tid];
            unsigned gt = 0;
            const float2* p2 = reinterpret_cast<const float2*>(s_cand);
            const unsigned np = (n_c + 1u) >> 1;
            #pragma unroll 4
            for (unsigned jp = 0; jp < np; ++jp) {
                float2 w2 = p2[jp];
                gt += (w2.x > c);
                gt += (w2.y > c);
            }
            if (gt == K - 1u) {
                atomicAdd(&s_ctrl[1], 1u);
                s_ctrl[0] = __float_as_uint(c);    // duplicates: identical bits
            }
        }
        __syncthreads();

        const unsigned m = s_ctrl[1];
        if (m >= 1u) {
            const float Ks = __uint_as_float(s_ctrl[0]);
            if (m == 1u) {
                // common case: keep iff v >= Ks
                #pragma unroll
                for (int i = 0; i < 4; ++i) {
                    float4 v4 = __ldg(xr + tid + i * 256);
                    float4 o;
                    o.x = (v4.x >= Ks) ? v4.x : 0.0f;
                    o.y = (v4.y >= Ks) ? v4.y : 0.0f;
                    o.z = (v4.z >= Ks) ? v4.z : 0.0f;
                    o.w = (v4.w >= Ks) ? v4.w : 0.0f;
                    orow[tid + i * 256] = o;
                }
                return;
            }
            // m > 1: budget is exactly 1 equal element -> lowest-index == Ks
            unsigned mc = 0xFFFFFFFFu;
            #pragma unroll
            for (int i = 0; i < 4; ++i) {
                float4 v4 = __ldg(xr + tid + i * 256);
                unsigned col0 = (unsigned)((i << 10) + (tid << 2));
                if (v4.x == Ks) mc = min(mc, col0 + 0u);
                if (v4.y == Ks) mc = min(mc, col0 + 1u);
                if (v4.z == Ks) mc = min(mc, col0 + 2u);
                if (v4.w == Ks) mc = min(mc, col0 + 3u);
            }
            mc = __reduce_min_sync(0xffffffffu, mc);
            if (lane == 0) s_wcnt[wid] = mc;
            __syncthreads();
            unsigned Ccut = 0xFFFFFFFFu;
            #pragma unroll
            for (int w = 0; w < 8; ++w) Ccut = min(Ccut, s_wcnt[w]);

            #pragma unroll
            for (int i = 0; i < 4; ++i) {
                float4 v4 = __ldg(xr + tid + i * 256);
                unsigned col0 = (unsigned)((i << 10) + (tid << 2));
                float4 o;
                o.x = ((v4.x > Ks) || (v4.x == Ks && (col0 + 0u) <= Ccut)) ? v4.x : 0.0f;
                o.y = ((v4.y > Ks) || (v4.y == Ks && (col0 + 1u) <= Ccut)) ? v4.y : 0.0f;
                o.z = ((v4.z > Ks) || (v4.z == Ks && (col0 + 2u) <= Ccut)) ? v4.z : 0.0f;
                o.w = ((v4.w > Ks) || (v4.w == Ks && (col0 + 3u) <= Ccut)) ? v4.w : 0.0f;
                orow[tid + i * 256] = o;
            }
            return;
        }
        // m == 0: tie group straddles K -> cold path
    }

    // ============== COLD PATH: exact key-domain radix select =============
    // All row reads are streamed (one float4 consumed at a time) to keep
    // register pressure at the hot path's level. Rare for the reference
    // distribution; exact for arbitrary data.
    __syncthreads();
    unsigned* s_ckey = reinterpret_cast<unsigned*>(s_cand);
    const uint4* __restrict__ xu = reinterpret_cast<const uint4*>(x) + row * (F_DIM / 4);

    unsigned lo = 0u, cnt_lo = F_DIM, cnt_hi1 = 0u;
    int shift = 32;

    #pragma unroll 1
    while (cnt_lo - cnt_hi1 > CAP && shift > 0) {
        unsigned q = 1u << (shift - 2);
        unsigned t1 = lo + q, t2 = lo + 2u * q, t3 = lo + 3u * q;
        unsigned c1 = 0, c2 = 0, c3 = 0;
        #pragma unroll 1
        for (int i = 0; i < 4; ++i) {
            uint4 b = __ldg(xu + tid + i * 256);
            unsigned k;
            k = f2key(b.x); c1 += (k >= t1); c2 += (k >= t2); c3 += (k >= t3);
            k = f2key(b.y); c1 += (k >= t1); c2 += (k >= t2); c3 += (k >= t3);
            k = f2key(b.z); c1 += (k >= t1); c2 += (k >= t2); c3 += (k >= t3);
            k = f2key(b.w); c1 += (k >= t1); c2 += (k >= t2); c3 += (k >= t3);
        }
        c1 = __reduce_add_sync(0xffffffffu, c1);
        c2 = __reduce_add_sync(0xffffffffu, c2);
        c3 = __reduce_add_sync(0xffffffffu, c3);
        if (lane == 0) { s_warp[wid][0] = c1; s_warp[wid][1] = c2; s_warp[wid][2] = c3; }
        __syncthreads();
        unsigned C1 = 0, C2 = 0, C3 = 0;
        #pragma unroll
        for (int w = 0; w < 8; ++w) { C1 += s_warp[w][0]; C2 += s_warp[w][1]; C3 += s_warp[w][2]; }
        __syncthreads();
        if      (C3 >= K) { lo = t3; cnt_lo = C3; }
        else if (C2 >= K) { lo = t2; cnt_lo = C2; cnt_hi1 = C3; }
        else if (C1 >= K) { lo = t1; cnt_lo = C1; cnt_hi1 = C2; }
        else              {                      cnt_hi1 = C1; }
        shift -= 2;
    }

    unsigned Kstar, c_ge, c_gt;
    if (shift == 0) {
        Kstar = lo; c_ge = cnt_lo; c_gt = cnt_hi1;
    } else {
        if (tid == 0) s_ctrl[7] = 0u;
        __syncthreads();
        const unsigned hib = lo + ((1u << shift) - 1u);
        #pragma unroll 1
        for (int i = 0; i < 4; ++i) {
            uint4 b = __ldg(xu + tid + i * 256);
            #pragma unroll
            for (int j = 0; j < 4; ++j) {
                unsigned k = f2key(j == 0 ? b.x : j == 1 ? b.y : j == 2 ? b.z : b.w);
                bool in = (k >= lo) && (k <= hib);
                unsigned mk = __ballot_sync(0xffffffffu, in);
                unsigned base = 0u;
                if (lane == 0) base = atomicAdd(&s_ctrl[7], (unsigned)__popc(mk));
                base = __shfl_sync(0xffffffffu, base, 0);
                if (in) {
                    unsigned p = base + (unsigned)__popc(mk & ((1u << lane) - 1u));
                    if (p < CAP) s_ckey[p] = k;
                }
            }
        }
        __syncthreads();

        const unsigned nc = s_ctrl[7];
        const unsigned A  = cnt_hi1;
        if ((unsigned)tid < nc) {
            unsigned ck = s_ckey[tid];
            unsigned gt = 0, ge = 0;
            #pragma unroll 4
            for (unsigned j = 0; j < nc; ++j) {
                unsigned vv = s_ckey[j];
                gt += (vv >  ck);
                ge += (vv >= ck);
            }
            unsigned GT = A + gt, GE = A + ge;
            if (GT < K && GE >= K) { s_ctrl[0] = ck; s_ctrl[2] = GE; s_ctrl[3] = GT; }
        }
        __syncthreads();
        Kstar = s_ctrl[0]; c_ge = s_ctrl[2]; c_gt = s_ctrl[3];
    }

    unsigned Ccut = 0xFFFFFFFFu;
    {
        unsigned budget = K - c_gt;
        unsigned c_eq   = c_ge - c_gt;
        if (budget < c_eq) {
            int loB = 0, hiB = F_DIM - 1;
            #pragma unroll 1
            while (loB < hiB) {
                int mid = (loB + hiB) >> 1;
                unsigned cc = 0;
                #pragma unroll 1
                for (int i = 0; i < 4; ++i) {
                    uint4 b = __ldg(xu + tid + i * 256);
                    unsigned col0 = (unsigned)((i << 10) + (tid << 2));
                    cc += (f2key(b.x) == Kstar && (int)(col0 + 0u) <= mid) ? 1u : 0u;
                    cc += (f2key(b.y) == Kstar && (int)(col0 + 1u) <= mid) ? 1u : 0u;
                    cc += (f2key(b.z) == Kstar && (int)(col0 + 2u) <= mid) ? 1u : 0u;
                    cc += (f2key(b.w) == Kstar && (int)(col0 + 3u) <= mid) ? 1u : 0u;
                }
                cc = __reduce_add_sync(0xffffffffu, cc);
                if (lane == 0) s_warp[wid][0] = cc;
                __syncthreads();
                unsigned Ct = 0;
                #pragma unroll
                for (int w = 0; w < 8; ++w) Ct += s_warp[w][0];
                __syncthreads();
                if (Ct >= budget) hiB = mid; else loB = mid + 1;
            }
            Ccut = (unsigned)loB;
        }
    }

    #pragma unroll 1
    for (int i = 0; i < 4; ++i) {
        uint4 b = __ldg(xu + tid + i * 256);
        unsigned col0 = (unsigned)((i << 10) + (tid << 2));
        unsigned k0 = f2key(b.x), k1 = f2key(b.y), k2 = f2key(b.z), k3 = f2key(b.w);
        uint4 o;
        o.x = ((k0 > Kstar) || (k0 == Kstar && (col0 + 0u) <= Ccut)) ? b.x : 0u;
        o.y = ((k1 > Kstar) || (k1 == Kstar && (col0 + 1u) <= Ccut)) ? b.y : 0u;
        o.z = ((k2 > Kstar) || (k2 == Kstar && (col0 + 2u) <= Ccut)) ? b.z : 0u;
        o.w = ((k3 > Kstar) || (k3 == Kstar && (col0 + 3u) <= Ccut)) ? b.w : 0u;
        reinterpret_cast<uint4*>(orow)[tid + i * 256] = o;
    }
}

extern "C" void kernel_launch(void* const* d_in, const int* in_sizes, int n_in,
                              void* d_out, int out_size)
{
    const float* x  = (const float*)d_in[0];
    const int*   kp = (n_in >= 2) ? (const int*)d_in[1] : nullptr;
    float* out = (float*)d_out;

    int B = in_sizes[0] / F_DIM;
    topk_mask_kernel<<<B, TPB>>>(x, kp, 64, out);
}